// round 3
// baseline (speedup 1.0000x reference)
#include <cuda_runtime.h>
#include <cuda_fp16.h>

// Sinkhorn B=128, N=M=1024, 10 iters. Memory-bound; K cached as fp16 (256MB).
//   iter0: read C fp32 -> K=exp(-20C) -> write K16, fused u/v-partial pass (v=1/M)
//   iter1..9: one K16 pass; warp owns 64 rows x 1024 cols; u via shfl; column
//             partials combined in smem; v reconstructed from prev partials.
//   k_final: reconstruct v, out = u * K16 * v.
// 64-thread blocks (2 warps), f32x2 packed math, K kept packed in uint4 regs.

#define Bb 128
#define Nn 1024
#define Mm 1024
#define CH 8            // row chunks per batch (block = 2 warps x 64 rows)
#define RPW 64          // rows per warp
#define EPS_STAB 1e-8f
#define NIE (-20.0f)

typedef unsigned long long ull;

__device__ __half g_K[(size_t)Bb * Nn * Mm];     // 256 MB
__device__ float  g_u[Bb * Nn];
__device__ float  g_vp[2][CH][Bb * Mm];          // double-buffered column partials

__device__ __forceinline__ ull pk2(float x, float y) {
    ull r; asm("mov.b64 %0,{%1,%2};" : "=l"(r) : "f"(x), "f"(y)); return r;
}
__device__ __forceinline__ float2 up2(ull a) {
    float2 f; asm("mov.b64 {%0,%1},%2;" : "=f"(f.x), "=f"(f.y) : "l"(a)); return f;
}
__device__ __forceinline__ ull ffma2(ull a, ull b, ull c) {
    ull d; asm("fma.rn.f32x2 %0,%1,%2,%3;" : "=l"(d) : "l"(a), "l"(b), "l"(c)); return d;
}
// half2 bits -> packed f32x2
__device__ __forceinline__ ull h2f2(unsigned h) {
    __half2 hh = *reinterpret_cast<__half2*>(&h);
    float2 f = __half22float2(hh);
    return pk2(f.x, f.y);
}

__device__ __forceinline__ float warp_sum(float p) {
#pragma unroll
    for (int o = 16; o; o >>= 1) p += __shfl_xor_sync(0xffffffffu, p, o);
    return p;
}

// dot(K_row, v) -> u; then vacc += K_row * u. K stays packed in q[4].
__device__ __forceinline__ void row_body(const uint4* q, const ull* vv, ull* va,
                                         float* uout, int l) {
    ull acc0 = pk2(0.f, 0.f), acc1 = acc0, acc2 = acc0, acc3 = acc0;
#pragma unroll
    for (int j = 0; j < 4; j++) {
        acc0 = ffma2(h2f2(q[j].x), vv[j*4+0], acc0);
        acc1 = ffma2(h2f2(q[j].y), vv[j*4+1], acc1);
        acc2 = ffma2(h2f2(q[j].z), vv[j*4+2], acc2);
        acc3 = ffma2(h2f2(q[j].w), vv[j*4+3], acc3);
    }
    float2 a0 = up2(acc0), a1 = up2(acc1), a2 = up2(acc2), a3 = up2(acc3);
    float p = ((a0.x + a0.y) + (a1.x + a1.y)) + ((a2.x + a2.y) + (a3.x + a3.y));
    p = warp_sum(p);
    float u = __fdividef(1.0f, p + EPS_STAB);
    if (l == 0) *uout = u;
    ull uu = pk2(u, u);
#pragma unroll
    for (int j = 0; j < 4; j++) {
        va[j*4+0] = ffma2(h2f2(q[j].x), uu, va[j*4+0]);
        va[j*4+1] = ffma2(h2f2(q[j].y), uu, va[j*4+1]);
        va[j*4+2] = ffma2(h2f2(q[j].z), uu, va[j*4+2]);
        va[j*4+3] = ffma2(h2f2(q[j].w), uu, va[j*4+3]);
    }
}

// cooperative v-reconstruct: 64 threads x 16 cols from CH chunk partials -> sv
__device__ __forceinline__ void reconstruct_v(float* sv, int pp, int b, int t) {
    float s[16];
#pragma unroll
    for (int i = 0; i < 16; i++) s[i] = 0.f;
#pragma unroll
    for (int c2 = 0; c2 < CH; c2++) {
        const float4* p4 = reinterpret_cast<const float4*>(&g_vp[pp][c2][b * Mm + t * 16]);
#pragma unroll
        for (int i = 0; i < 4; i++) {
            float4 a = p4[i];
            s[i*4+0] += a.x; s[i*4+1] += a.y; s[i*4+2] += a.z; s[i*4+3] += a.w;
        }
    }
#pragma unroll
    for (int i = 0; i < 16; i++) sv[t * 16 + i] = __fdividef(1.0f, s[i] + EPS_STAB);
}

// ---------------------------------------------------------------- fused iter
template<bool FIRST>
__global__ void __launch_bounds__(64, FIRST ? 8 : 9)
k_iter(const float* __restrict__ C, int par) {
    const int t = threadIdx.x, l = t & 31, w = t >> 5;
    const int c = blockIdx.x, b = blockIdx.y;
    const int row0  = c * (2 * RPW) + w * RPW;
    const int nbase = b * Nn + row0;

    __shared__ float sv[Mm];
    __shared__ float sva[2][Mm];

    ull vv[16];
    if (!FIRST) {
        reconstruct_v(sv, par ^ 1, b, t);
        __syncthreads();
        const float2* svp = reinterpret_cast<const float2*>(sv);
#pragma unroll
        for (int j = 0; j < 4; j++)
#pragma unroll
            for (int p = 0; p < 4; p++) {
                float2 f = svp[(j * 256 + l * 8) / 2 + p];
                vv[j*4+p] = pk2(f.x, f.y);
            }
    } else {
#pragma unroll
        for (int i = 0; i < 16; i++) vv[i] = pk2(1.0f / Mm, 1.0f / Mm);
    }

    ull va[16];
#pragma unroll
    for (int i = 0; i < 16; i++) va[i] = pk2(0.f, 0.f);

    const size_t base = (size_t)nbase * Mm;

    if (FIRST) {
        const float4* Cp = reinterpret_cast<const float4*>(C + base);
        uint4* Kw = reinterpret_cast<uint4*>(g_K + base);
        for (int r = 0; r < RPW; ++r) {
            uint4 q[4];
#pragma unroll
            for (int j = 0; j < 4; j++) {
                float4 a = Cp[r*256 + j*64 + l*2];
                float4 d = Cp[r*256 + j*64 + l*2 + 1];
                __half2 h0 = __floats2half2_rn(__expf(NIE*a.x), __expf(NIE*a.y));
                __half2 h1 = __floats2half2_rn(__expf(NIE*a.z), __expf(NIE*a.w));
                __half2 h2 = __floats2half2_rn(__expf(NIE*d.x), __expf(NIE*d.y));
                __half2 h3 = __floats2half2_rn(__expf(NIE*d.z), __expf(NIE*d.w));
                q[j].x = *reinterpret_cast<unsigned*>(&h0);
                q[j].y = *reinterpret_cast<unsigned*>(&h1);
                q[j].z = *reinterpret_cast<unsigned*>(&h2);
                q[j].w = *reinterpret_cast<unsigned*>(&h3);
                Kw[r*128 + j*32 + l] = q[j];
            }
            row_body(q, vv, va, &g_u[nbase + r], l);
        }
    } else {
        const uint4* Kp = reinterpret_cast<const uint4*>(g_K + base);
        uint4 q[4], qn[4];
#pragma unroll
        for (int j = 0; j < 4; j++) q[j] = Kp[j*32 + l];
        for (int r = 0; r < RPW; ++r) {
            const int rn = (r + 1 < RPW) ? r + 1 : r;
#pragma unroll
            for (int j = 0; j < 4; j++) qn[j] = Kp[rn*128 + j*32 + l];
            row_body(q, vv, va, &g_u[nbase + r], l);
#pragma unroll
            for (int j = 0; j < 4; j++) q[j] = qn[j];
        }
    }

    // combine the 2 warps' column partials -> this chunk's partial
#pragma unroll
    for (int j = 0; j < 4; j++)
#pragma unroll
        for (int p = 0; p < 4; p++) {
            float2 f = up2(va[j*4+p]);
            sva[w][j*256 + l*8 + 2*p]     = f.x;
            sva[w][j*256 + l*8 + 2*p + 1] = f.y;
        }
    __syncthreads();
    float4* outp = reinterpret_cast<float4*>(&g_vp[par][c][b * Mm + t * 16]);
    const float4* s0 = reinterpret_cast<const float4*>(&sva[0][t * 16]);
    const float4* s1 = reinterpret_cast<const float4*>(&sva[1][t * 16]);
#pragma unroll
    for (int i = 0; i < 4; i++) {
        float4 a = s0[i], d = s1[i];
        a.x += d.x; a.y += d.y; a.z += d.z; a.w += d.w;
        outp[i] = a;
    }
}

// ---------------------------------------------------------------- final out
__global__ void __launch_bounds__(64, 8) k_final(float* __restrict__ out) {
    const int t = threadIdx.x, l = t & 31, w = t >> 5;
    const int c = blockIdx.x, b = blockIdx.y;

    __shared__ float sv[Mm];
    reconstruct_v(sv, 1, b, t);          // iter9 wrote par=1
    __syncthreads();

    float vf[32];
#pragma unroll
    for (int j = 0; j < 4; j++)
#pragma unroll
        for (int e = 0; e < 8; e++) vf[j*8+e] = sv[j*256 + l*8 + e];

    const int row0 = c * (2 * RPW) + w * RPW;
    const size_t base = (size_t)(b * Nn + row0) * Mm;
    const uint4* Kp = reinterpret_cast<const uint4*>(g_K + base);
    float4* op = reinterpret_cast<float4*>(out + base);

    uint4 q[4], qn[4];
#pragma unroll
    for (int j = 0; j < 4; j++) q[j] = Kp[j*32 + l];
    for (int r = 0; r < RPW; ++r) {
        const int rn = (r + 1 < RPW) ? r + 1 : r;
#pragma unroll
        for (int j = 0; j < 4; j++) qn[j] = Kp[rn*128 + j*32 + l];
        float u = g_u[b * Nn + row0 + r];
#pragma unroll
        for (int j = 0; j < 4; j++) {
            float2 k0 = __half22float2(*reinterpret_cast<__half2*>(&q[j].x));
            float2 k1 = __half22float2(*reinterpret_cast<__half2*>(&q[j].y));
            float2 k2 = __half22float2(*reinterpret_cast<__half2*>(&q[j].z));
            float2 k3 = __half22float2(*reinterpret_cast<__half2*>(&q[j].w));
            float4 o0, o1;
            o0.x = u * k0.x * vf[j*8+0]; o0.y = u * k0.y * vf[j*8+1];
            o0.z = u * k1.x * vf[j*8+2]; o0.w = u * k1.y * vf[j*8+3];
            o1.x = u * k2.x * vf[j*8+4]; o1.y = u * k2.y * vf[j*8+5];
            o1.z = u * k3.x * vf[j*8+6]; o1.w = u * k3.y * vf[j*8+7];
            op[r*256 + j*64 + l*2]     = o0;
            op[r*256 + j*64 + l*2 + 1] = o1;
        }
#pragma unroll
        for (int j = 0; j < 4; j++) q[j] = qn[j];
    }
}

// ---------------------------------------------------------------- launch
extern "C" void kernel_launch(void* const* d_in, const int* in_sizes, int n_in,
                              void* d_out, int out_size) {
    const float* C = (const float*)d_in[0];
    float* out = (float*)d_out;

    k_iter<true><<<dim3(CH, Bb), 64>>>(C, 0);
    for (int it = 1; it < 10; ++it)
        k_iter<false><<<dim3(CH, Bb), 64>>>(C, it & 1);
    k_final<<<dim3(CH, Bb), 64>>>(out);
}